// round 1
// baseline (speedup 1.0000x reference)
#include <cuda_runtime.h>
#include <cuda_bf16.h>

typedef unsigned long long ull;

// ---------------- scratch (no allocation allowed) ----------------
__device__ float g_att_h[256 * 1024];     // [B, 2*ATT_HID]
__device__ float g_weight[256 * 196];     // softmax weights
__device__ float g_att_res[256 * 2048];   // weighted att features
__device__ float g_lin2[256 * 2048];      // att_res @ W_out + b

// ---------------- helpers ----------------
__device__ __forceinline__ void fma2(ull& acc, ull a, ull b) {
    asm("fma.rn.f32x2 %0, %1, %2, %0;" : "+l"(acc) : "l"(a), "l"(b));
}
__device__ __forceinline__ float2 unpk(ull v) {
    float2 r;
    asm("mov.b64 {%0, %1}, %2;" : "=f"(r.x), "=f"(r.y) : "l"(v));
    return r;
}
__device__ __forceinline__ float fast_tanh(float x) {
    float t; asm("tanh.approx.f32 %0, %1;" : "=f"(t) : "f"(x)); return t;
}
__device__ __forceinline__ float fast_ex2(float x) {
    float t; asm("ex2.approx.f32 %0, %1;" : "=f"(t) : "f"(x)); return t;
}
__device__ __forceinline__ float fast_rcp(float x) {
    float t; asm("rcp.approx.f32 %0, %1;" : "=f"(t) : "f"(x)); return t;
}
__device__ __forceinline__ float gatef(float u, float v) {
    // tanh(u) * sigmoid(v)
    float e = fast_ex2(-1.44269504f * v);
    return fast_tanh(u) * fast_rcp(1.0f + e);
}

// ---------------- GEMM: C[64*gy : , 64*gx : ] = A @ B + bias ----------------
// A: [M, K] row-major (M = gridDim.y*64), B: [K, N] row-major, bias: [N]
// BM=BN=64, BK=16, 256 threads, 4x4 per thread via packed f32x2 FMA.
__global__ void __launch_bounds__(256) gemm_bias_kernel(
    const float* __restrict__ A, const float* __restrict__ B,
    const float* __restrict__ bias, float* __restrict__ C,
    int N, int K)
{
    __shared__ float As2[16][128];  // duplicated: As2[k][2m]=As2[k][2m+1]=A[m][k]
    __shared__ float Bs[16][64];

    const int tid = threadIdx.x;
    const int tx = tid & 15;        // 0..15 -> 4 cols each
    const int ty = tid >> 4;        // 0..15 -> 4 rows each

    const int mload = tid >> 2;             // 0..63 (row within tile for A load)
    const int kgrp  = (tid & 3) << 2;       // 0,4,8,12
    const float* Aptr = A + (size_t)(((size_t)blockIdx.y << 6) + mload) * K + kgrp;

    const int krow = tid >> 4;              // 0..15 (k row for B load)
    const int colB = ((int)blockIdx.x << 6) + ((tid & 15) << 2);
    const float* Bptr = B + (size_t)krow * N + colB;

    ull acc[4][2];
#pragma unroll
    for (int i = 0; i < 4; i++) { acc[i][0] = 0ull; acc[i][1] = 0ull; }

    for (int kt = 0; kt < K; kt += 16) {
        float4 av = *(const float4*)(Aptr + kt);
        float4 bv = *(const float4*)(Bptr + (size_t)kt * N);
        __syncthreads();
        *(float2*)&As2[kgrp + 0][2 * mload] = make_float2(av.x, av.x);
        *(float2*)&As2[kgrp + 1][2 * mload] = make_float2(av.y, av.y);
        *(float2*)&As2[kgrp + 2][2 * mload] = make_float2(av.z, av.z);
        *(float2*)&As2[kgrp + 3][2 * mload] = make_float2(av.w, av.w);
        *(float4*)&Bs[krow][(tid & 15) << 2] = bv;
        __syncthreads();
#pragma unroll
        for (int k = 0; k < 16; k++) {
            ulonglong2 aa0 = *(const ulonglong2*)&As2[k][(ty << 3)];
            ulonglong2 aa1 = *(const ulonglong2*)&As2[k][(ty << 3) + 4];
            ulonglong2 bb  = *(const ulonglong2*)&Bs[k][tx << 2];
            fma2(acc[0][0], aa0.x, bb.x); fma2(acc[0][1], aa0.x, bb.y);
            fma2(acc[1][0], aa0.y, bb.x); fma2(acc[1][1], aa0.y, bb.y);
            fma2(acc[2][0], aa1.x, bb.x); fma2(acc[2][1], aa1.x, bb.y);
            fma2(acc[3][0], aa1.y, bb.x); fma2(acc[3][1], aa1.y, bb.y);
        }
    }

    const int colOut = ((int)blockIdx.x << 6) + (tx << 2);
    float4 bs = *(const float4*)(bias + colOut);
#pragma unroll
    for (int i = 0; i < 4; i++) {
        int row = ((int)blockIdx.y << 6) + (ty << 2) + i;
        float2 c0 = unpk(acc[i][0]);
        float2 c1 = unpk(acc[i][1]);
        float4 o = make_float4(c0.x + bs.x, c0.y + bs.y, c1.x + bs.z, c1.y + bs.w);
        *(float4*)&C[(size_t)row * N + colOut] = o;
    }
}

// ---------------- scores + softmax ----------------
// One block per batch row. scores[s] = sum_j tanh(p1+ah1)*sigmoid(p2+ah2)*wa[j] + b_alpha
__global__ void __launch_bounds__(256) scores_softmax_kernel(
    const float* __restrict__ p_att, const float* __restrict__ att_h,
    const float* __restrict__ w_alpha, const float* __restrict__ b_alpha,
    float* __restrict__ weight)
{
    __shared__ float ah[1024];
    __shared__ float wa[512];
    __shared__ float sc[200];
    __shared__ float redm[8], reds[8];

    const int b = blockIdx.x;
    const int tid = threadIdx.x;
    for (int i = tid; i < 1024; i += 256) ah[i] = att_h[b * 1024 + i];
    for (int i = tid; i < 512; i += 256)  wa[i] = w_alpha[i];
    __syncthreads();

    const int lane = tid & 31, warp = tid >> 5;
    const float4* ah1 = (const float4*)ah;
    const float4* ah2 = ah1 + 128;
    const float4* wav = (const float4*)wa;
    const float balpha = b_alpha[0];

    for (int s = warp; s < 196; s += 8) {
        const float4* p = (const float4*)(p_att + ((size_t)b * 196 + s) * 1024);
        float sum = 0.0f;
#pragma unroll
        for (int i = 0; i < 4; i++) {
            int j = lane + (i << 5);
            float4 x = p[j];
            float4 y = p[j + 128];
            float4 a1 = ah1[j];
            float4 a2 = ah2[j];
            float4 w4 = wav[j];
            sum += gatef(x.x + a1.x, y.x + a2.x) * w4.x;
            sum += gatef(x.y + a1.y, y.y + a2.y) * w4.y;
            sum += gatef(x.z + a1.z, y.z + a2.z) * w4.z;
            sum += gatef(x.w + a1.w, y.w + a2.w) * w4.w;
        }
#pragma unroll
        for (int off = 16; off > 0; off >>= 1)
            sum += __shfl_xor_sync(0xffffffffu, sum, off);
        if (lane == 0) sc[s] = sum + balpha;
    }
    __syncthreads();

    // softmax over 196 scores
    float v = (tid < 196) ? sc[tid] : -1e30f;
    float m = v;
#pragma unroll
    for (int off = 16; off > 0; off >>= 1)
        m = fmaxf(m, __shfl_xor_sync(0xffffffffu, m, off));
    if (lane == 0) redm[warp] = m;
    __syncthreads();
    float mall = redm[0];
#pragma unroll
    for (int i = 1; i < 8; i++) mall = fmaxf(mall, redm[i]);

    float e = (tid < 196) ? fast_ex2(1.44269504f * (v - mall)) : 0.0f;
    float ssum = e;
#pragma unroll
    for (int off = 16; off > 0; off >>= 1)
        ssum += __shfl_xor_sync(0xffffffffu, ssum, off);
    if (lane == 0) reds[warp] = ssum;
    __syncthreads();
    float tot = 0.0f;
#pragma unroll
    for (int i = 0; i < 8; i++) tot += reds[i];

    if (tid < 196) weight[b * 196 + tid] = e / tot;
}

// ---------------- att_res = weight @ att_feats ----------------
// grid (2, 256): blockIdx.y = batch, blockIdx.x = which 1024-float half.
__global__ void __launch_bounds__(256) att_reduce_kernel(
    const float* __restrict__ att_feats, const float* __restrict__ weight,
    float* __restrict__ att_res)
{
    __shared__ float w[196];
    const int b = blockIdx.y;
    const int half = blockIdx.x;
    const int tid = threadIdx.x;
    for (int i = tid; i < 196; i += 256) w[i] = weight[b * 196 + i];
    __syncthreads();

    const float4* base = (const float4*)(att_feats + (size_t)b * 196 * 2048 + half * 1024) + tid;
    float4 acc = make_float4(0.f, 0.f, 0.f, 0.f);
#pragma unroll 4
    for (int s = 0; s < 196; s++) {
        float4 vv = base[(size_t)s * 512];
        float ws = w[s];
        acc.x += ws * vv.x; acc.y += ws * vv.y;
        acc.z += ws * vv.z; acc.w += ws * vv.w;
    }
    *(float4*)&att_res[(size_t)b * 2048 + half * 1024 + tid * 4] = acc;
}

// ---------------- final GLU gate (accurate math) ----------------
__global__ void __launch_bounds__(256) glu_kernel(
    const float* __restrict__ C, float* __restrict__ out)
{
    int idx = blockIdx.x * 256 + threadIdx.x;   // 0 .. 262143
    int b = idx >> 10, j = idx & 1023;
    float x = C[(size_t)b * 2048 + j];
    float y = C[(size_t)b * 2048 + 1024 + j];
    out[idx] = tanhf(x) * (1.0f / (1.0f + expf(-y)));
}

// ---------------- launch ----------------
extern "C" void kernel_launch(void* const* d_in, const int* in_sizes, int n_in,
                              void* d_out, int out_size)
{
    const float* h         = (const float*)d_in[0];
    const float* att_feats = (const float*)d_in[1];
    const float* p_att     = (const float*)d_in[2];
    const float* W_h2att   = (const float*)d_in[3];
    const float* b_h2att   = (const float*)d_in[4];
    const float* w_alpha   = (const float*)d_in[5];
    const float* b_alpha   = (const float*)d_in[6];
    const float* W_out     = (const float*)d_in[7];
    const float* b_out     = (const float*)d_in[8];
    float* out = (float*)d_out;

    float *att_h_p, *weight_p, *att_res_p, *lin2_p;
    cudaGetSymbolAddress((void**)&att_h_p,   g_att_h);
    cudaGetSymbolAddress((void**)&weight_p,  g_weight);
    cudaGetSymbolAddress((void**)&att_res_p, g_att_res);
    cudaGetSymbolAddress((void**)&lin2_p,    g_lin2);

    // 1) att_h = h @ W_h2att + b      [256,1024] x [1024,1024]
    gemm_bias_kernel<<<dim3(16, 4), 256>>>(h, W_h2att, b_h2att, att_h_p, 1024, 1024);
    // 2) gated scores + softmax -> weights [256,196]
    scores_softmax_kernel<<<256, 256>>>(p_att, att_h_p, w_alpha, b_alpha, weight_p);
    // 3) att_res = weight @ att_feats  [256,2048]
    att_reduce_kernel<<<dim3(2, 256), 256>>>(att_feats, weight_p, att_res_p);
    // 4) lin2 = att_res @ W_out + b    [256,2048] x [2048,2048]
    gemm_bias_kernel<<<dim3(32, 4), 256>>>(att_res_p, W_out, b_out, lin2_p, 2048, 2048);
    // 5) out = tanh(lin2[:, :1024]) * sigmoid(lin2[:, 1024:])
    glu_kernel<<<1024, 256>>>(lin2_p, out);
}

// round 2
// speedup vs baseline: 1.0631x; 1.0631x over previous
#include <cuda_runtime.h>
#include <cuda_bf16.h>

typedef unsigned long long ull;

// ---------------- scratch (no allocation allowed) ----------------
__device__ float g_att_h[256 * 1024];     // [B, 2*ATT_HID]
__device__ float g_weight[256 * 196];     // softmax weights
__device__ float g_att_res[256 * 2048];   // weighted att features
__device__ float g_lin2[256 * 2048];      // att_res @ W_out + b

// ---------------- helpers ----------------
__device__ __forceinline__ void fma2(ull& acc, ull a, ull b) {
    asm("fma.rn.f32x2 %0, %1, %2, %0;" : "+l"(acc) : "l"(a), "l"(b));
}
__device__ __forceinline__ float2 unpk(ull v) {
    float2 r;
    asm("mov.b64 {%0, %1}, %2;" : "=f"(r.x), "=f"(r.y) : "l"(v));
    return r;
}
__device__ __forceinline__ float fast_tanh(float x) {
    float t; asm("tanh.approx.f32 %0, %1;" : "=f"(t) : "f"(x)); return t;
}
__device__ __forceinline__ float fast_ex2(float x) {
    float t; asm("ex2.approx.f32 %0, %1;" : "=f"(t) : "f"(x)); return t;
}
__device__ __forceinline__ float fast_rcp(float x) {
    float t; asm("rcp.approx.f32 %0, %1;" : "=f"(t) : "f"(x)); return t;
}
__device__ __forceinline__ float gatef(float u, float v) {
    // tanh(u) * sigmoid(v)
    float e = fast_ex2(-1.44269504f * v);
    return fast_tanh(u) * fast_rcp(1.0f + e);
}

// ---------------- GEMM: C[64*gy : , 64*gx : ] = A @ B + bias ----------------
// A: [M, K] row-major, B: [K, N] row-major, bias: [N]
// BM=BN=64, BK=16, 256 threads, 4x4 per thread via packed f32x2 FMA.
// Software-pipelined: register prefetch of next global tile + double-buffered
// SMEM, single __syncthreads per iteration.
__global__ void __launch_bounds__(256) gemm_bias_kernel(
    const float* __restrict__ A, const float* __restrict__ B,
    const float* __restrict__ bias, float* __restrict__ C,
    int N, int K)
{
    // padded rows: 132*4B=528B (16B aligned, 2-way STS conflict instead of 4),
    // 68*4B=272B (16B aligned)
    __shared__ float As2[2][16][132];  // duplicated (a,a) pairs per element
    __shared__ float Bs[2][16][68];

    const int tid = threadIdx.x;
    const int tx = tid & 15;        // 0..15 -> 4 cols each
    const int ty = tid >> 4;        // 0..15 -> 4 rows each

    const int mload = tid >> 2;             // 0..63 (A row within tile)
    const int kgrp  = (tid & 3) << 2;       // 0,4,8,12
    const float* Aptr = A + (size_t)(((size_t)blockIdx.y << 6) + mload) * K + kgrp;

    const int krow = tid >> 4;              // 0..15 (B k-row)
    const int colB = ((int)blockIdx.x << 6) + (tx << 2);
    const float* Bptr = B + (size_t)krow * N + colB;

    ull acc[4][2];
#pragma unroll
    for (int i = 0; i < 4; i++) { acc[i][0] = 0ull; acc[i][1] = 0ull; }

    // prologue prefetch
    float4 av = *(const float4*)(Aptr);
    float4 bv = *(const float4*)(Bptr);

    int buf = 0;
    for (int kt = 0; kt < K; kt += 16) {
        // stage current tile into smem[buf]
        *(float2*)&As2[buf][kgrp + 0][2 * mload] = make_float2(av.x, av.x);
        *(float2*)&As2[buf][kgrp + 1][2 * mload] = make_float2(av.y, av.y);
        *(float2*)&As2[buf][kgrp + 2][2 * mload] = make_float2(av.z, av.z);
        *(float2*)&As2[buf][kgrp + 3][2 * mload] = make_float2(av.w, av.w);
        *(float4*)&Bs[buf][krow][tx << 2] = bv;
        __syncthreads();

        // prefetch next global tile (latency overlapped with compute below)
        if (kt + 16 < K) {
            av = *(const float4*)(Aptr + kt + 16);
            bv = *(const float4*)(Bptr + (size_t)(kt + 16) * N);
        }

#pragma unroll
        for (int k = 0; k < 16; k++) {
            ulonglong2 aa0 = *(const ulonglong2*)&As2[buf][k][(ty << 3)];
            ulonglong2 aa1 = *(const ulonglong2*)&As2[buf][k][(ty << 3) + 4];
            ulonglong2 bb  = *(const ulonglong2*)&Bs[buf][k][tx << 2];
            fma2(acc[0][0], aa0.x, bb.x); fma2(acc[0][1], aa0.x, bb.y);
            fma2(acc[1][0], aa0.y, bb.x); fma2(acc[1][1], aa0.y, bb.y);
            fma2(acc[2][0], aa1.x, bb.x); fma2(acc[2][1], aa1.x, bb.y);
            fma2(acc[3][0], aa1.y, bb.x); fma2(acc[3][1], aa1.y, bb.y);
        }
        buf ^= 1;
        // note: writes in next iter go to buf^1, last read two iters ago and
        // fenced by the barrier above — one sync per iteration is sufficient.
    }

    const int colOut = ((int)blockIdx.x << 6) + (tx << 2);
    float4 bs = *(const float4*)(bias + colOut);
#pragma unroll
    for (int i = 0; i < 4; i++) {
        int row = ((int)blockIdx.y << 6) + (ty << 2) + i;
        float2 c0 = unpk(acc[i][0]);
        float2 c1 = unpk(acc[i][1]);
        float4 o = make_float4(c0.x + bs.x, c0.y + bs.y, c1.x + bs.z, c1.y + bs.w);
        *(float4*)&C[(size_t)row * N + colOut] = o;
    }
}

// ---------------- scores + softmax ----------------
// One block per batch row. scores[s] = sum_j tanh(p1+ah1)*sigmoid(p2+ah2)*wa[j] + b_alpha
__global__ void __launch_bounds__(256) scores_softmax_kernel(
    const float* __restrict__ p_att, const float* __restrict__ att_h,
    const float* __restrict__ w_alpha, const float* __restrict__ b_alpha,
    float* __restrict__ weight)
{
    __shared__ float ah[1024];
    __shared__ float wa[512];
    __shared__ float sc[200];
    __shared__ float redm[8], reds[8];

    const int b = blockIdx.x;
    const int tid = threadIdx.x;
    for (int i = tid; i < 1024; i += 256) ah[i] = att_h[b * 1024 + i];
    for (int i = tid; i < 512; i += 256)  wa[i] = w_alpha[i];
    __syncthreads();

    const int lane = tid & 31, warp = tid >> 5;
    const float4* ah1 = (const float4*)ah;
    const float4* ah2 = ah1 + 128;
    const float4* wav = (const float4*)wa;
    const float balpha = b_alpha[0];

    for (int s = warp; s < 196; s += 8) {
        const float4* p = (const float4*)(p_att + ((size_t)b * 196 + s) * 1024);
        float sum = 0.0f;
#pragma unroll
        for (int i = 0; i < 4; i++) {
            int j = lane + (i << 5);
            float4 x = p[j];
            float4 y = p[j + 128];
            float4 a1 = ah1[j];
            float4 a2 = ah2[j];
            float4 w4 = wav[j];
            sum += gatef(x.x + a1.x, y.x + a2.x) * w4.x;
            sum += gatef(x.y + a1.y, y.y + a2.y) * w4.y;
            sum += gatef(x.z + a1.z, y.z + a2.z) * w4.z;
            sum += gatef(x.w + a1.w, y.w + a2.w) * w4.w;
        }
#pragma unroll
        for (int off = 16; off > 0; off >>= 1)
            sum += __shfl_xor_sync(0xffffffffu, sum, off);
        if (lane == 0) sc[s] = sum + balpha;
    }
    __syncthreads();

    // softmax over 196 scores
    float v = (tid < 196) ? sc[tid] : -1e30f;
    float m = v;
#pragma unroll
    for (int off = 16; off > 0; off >>= 1)
        m = fmaxf(m, __shfl_xor_sync(0xffffffffu, m, off));
    if (lane == 0) redm[warp] = m;
    __syncthreads();
    float mall = redm[0];
#pragma unroll
    for (int i = 1; i < 8; i++) mall = fmaxf(mall, redm[i]);

    float e = (tid < 196) ? fast_ex2(1.44269504f * (v - mall)) : 0.0f;
    float ssum = e;
#pragma unroll
    for (int off = 16; off > 0; off >>= 1)
        ssum += __shfl_xor_sync(0xffffffffu, ssum, off);
    if (lane == 0) reds[warp] = ssum;
    __syncthreads();
    float tot = 0.0f;
#pragma unroll
    for (int i = 0; i < 8; i++) tot += reds[i];

    if (tid < 196) weight[b * 196 + tid] = e / tot;
}

// ---------------- att_res = weight @ att_feats ----------------
// grid (2, 256): blockIdx.y = batch, blockIdx.x = which 1024-float half.
__global__ void __launch_bounds__(256) att_reduce_kernel(
    const float* __restrict__ att_feats, const float* __restrict__ weight,
    float* __restrict__ att_res)
{
    __shared__ float w[196];
    const int b = blockIdx.y;
    const int half = blockIdx.x;
    const int tid = threadIdx.x;
    for (int i = tid; i < 196; i += 256) w[i] = weight[b * 196 + i];
    __syncthreads();

    const float4* base = (const float4*)(att_feats + (size_t)b * 196 * 2048 + half * 1024) + tid;
    float4 acc = make_float4(0.f, 0.f, 0.f, 0.f);
#pragma unroll 4
    for (int s = 0; s < 196; s++) {
        float4 vv = base[(size_t)s * 512];
        float ws = w[s];
        acc.x += ws * vv.x; acc.y += ws * vv.y;
        acc.z += ws * vv.z; acc.w += ws * vv.w;
    }
    *(float4*)&att_res[(size_t)b * 2048 + half * 1024 + tid * 4] = acc;
}

// ---------------- final GLU gate (accurate math) ----------------
__global__ void __launch_bounds__(256) glu_kernel(
    const float* __restrict__ C, float* __restrict__ out)
{
    int idx = blockIdx.x * 256 + threadIdx.x;   // 0 .. 262143
    int b = idx >> 10, j = idx & 1023;
    float x = C[(size_t)b * 2048 + j];
    float y = C[(size_t)b * 2048 + 1024 + j];
    out[idx] = tanhf(x) * (1.0f / (1.0f + expf(-y)));
}

// ---------------- launch ----------------
extern "C" void kernel_launch(void* const* d_in, const int* in_sizes, int n_in,
                              void* d_out, int out_size)
{
    const float* h         = (const float*)d_in[0];
    const float* att_feats = (const float*)d_in[1];
    const float* p_att     = (const float*)d_in[2];
    const float* W_h2att   = (const float*)d_in[3];
    const float* b_h2att   = (const float*)d_in[4];
    const float* w_alpha   = (const float*)d_in[5];
    const float* b_alpha   = (const float*)d_in[6];
    const float* W_out     = (const float*)d_in[7];
    const float* b_out     = (const float*)d_in[8];
    float* out = (float*)d_out;

    float *att_h_p, *weight_p, *att_res_p, *lin2_p;
    cudaGetSymbolAddress((void**)&att_h_p,   g_att_h);
    cudaGetSymbolAddress((void**)&weight_p,  g_weight);
    cudaGetSymbolAddress((void**)&att_res_p, g_att_res);
    cudaGetSymbolAddress((void**)&lin2_p,    g_lin2);

    // 1) att_h = h @ W_h2att + b      [256,1024] x [1024,1024]
    gemm_bias_kernel<<<dim3(16, 4), 256>>>(h, W_h2att, b_h2att, att_h_p, 1024, 1024);
    // 2) gated scores + softmax -> weights [256,196]
    scores_softmax_kernel<<<256, 256>>>(p_att, att_h_p, w_alpha, b_alpha, weight_p);
    // 3) att_res = weight @ att_feats  [256,2048]
    att_reduce_kernel<<<dim3(2, 256), 256>>>(att_feats, weight_p, att_res_p);
    // 4) lin2 = att_res @ W_out + b    [256,2048] x [2048,2048]
    gemm_bias_kernel<<<dim3(32, 4), 256>>>(att_res_p, W_out, b_out, lin2_p, 2048, 2048);
    // 5) out = tanh(lin2[:, :1024]) * sigmoid(lin2[:, 1024:])
    glu_kernel<<<1024, 256>>>(lin2_p, out);
}

// round 5
// speedup vs baseline: 1.6860x; 1.5860x over previous
#include <cuda_runtime.h>
#include <cuda_bf16.h>
#include <cstdint>

// ---------------- scratch (no allocation allowed) ----------------
__device__ float g_att_h[256 * 1024];
__device__ float g_weight[256 * 196];
__device__ float g_lin2[256 * 2048];
__device__ __nv_bfloat16 g_WT1h[1024 * 1024];
__device__ __nv_bfloat16 g_WT1l[1024 * 1024];
__device__ __nv_bfloat16 g_WT2h[2048 * 2048];
__device__ __nv_bfloat16 g_WT2l[2048 * 2048];
__device__ __nv_bfloat16 g_hh[256 * 1024];
__device__ __nv_bfloat16 g_hl[256 * 1024];
__device__ __nv_bfloat16 g_arh[256 * 2048];
__device__ __nv_bfloat16 g_arl[256 * 2048];

// ---------------- helpers ----------------
__device__ __forceinline__ uint32_t smem_u32(const void* p) {
    uint32_t a;
    asm("{ .reg .u64 t; cvta.to.shared.u64 t, %1; cvt.u32.u64 %0, t; }" : "=r"(a) : "l"(p));
    return a;
}
__device__ __forceinline__ void ldsm4(uint32_t* r, uint32_t addr) {
    asm volatile("ldmatrix.sync.aligned.m8n8.x4.shared.b16 {%0,%1,%2,%3}, [%4];"
                 : "=r"(r[0]), "=r"(r[1]), "=r"(r[2]), "=r"(r[3]) : "r"(addr));
}
__device__ __forceinline__ void mma16816(float* d, const uint32_t* a, const uint32_t* b) {
    asm volatile(
        "mma.sync.aligned.m16n8k16.row.col.f32.bf16.bf16.f32 "
        "{%0,%1,%2,%3}, {%4,%5,%6,%7}, {%8,%9}, {%0,%1,%2,%3};"
        : "+f"(d[0]), "+f"(d[1]), "+f"(d[2]), "+f"(d[3])
        : "r"(a[0]), "r"(a[1]), "r"(a[2]), "r"(a[3]), "r"(b[0]), "r"(b[1]));
}
__device__ __forceinline__ float fast_tanh(float x) {
    float t; asm("tanh.approx.f32 %0, %1;" : "=f"(t) : "f"(x)); return t;
}
__device__ __forceinline__ float fast_ex2(float x) {
    float t; asm("ex2.approx.f32 %0, %1;" : "=f"(t) : "f"(x)); return t;
}
__device__ __forceinline__ float fast_rcp(float x) {
    float t; asm("rcp.approx.f32 %0, %1;" : "=f"(t) : "f"(x)); return t;
}
__device__ __forceinline__ float gatef(float u, float v) {
    float e = fast_ex2(-1.44269504f * v);
    return fast_tanh(u) * fast_rcp(1.0f + e);
}

// ---------------- prep: transpose + bf16 hi/lo split of W [K,N] -> WT [N,K] ----------------
__global__ void __launch_bounds__(256) prep_WT_kernel(
    const float* __restrict__ W, __nv_bfloat16* __restrict__ WTh,
    __nv_bfloat16* __restrict__ WTl, int K, int N)
{
    __shared__ float t[32][33];
    int kx = blockIdx.y * 32, nx = blockIdx.x * 32;
    int tx = threadIdx.x & 31, ty = threadIdx.x >> 5;  // ty 0..7
#pragma unroll
    for (int i = 0; i < 32; i += 8)
        t[ty + i][tx] = W[(size_t)(kx + ty + i) * N + nx + tx];
    __syncthreads();
#pragma unroll
    for (int i = 0; i < 32; i += 8) {
        float v = t[tx][ty + i];
        __nv_bfloat16 h = __float2bfloat16(v);
        __nv_bfloat16 l = __float2bfloat16(v - __bfloat162float(h));
        size_t o = (size_t)(nx + ty + i) * K + kx + tx;
        WTh[o] = h;
        WTl[o] = l;
    }
}

// ---------------- prep: elementwise bf16 hi/lo split ----------------
__global__ void __launch_bounds__(256) prep_split_kernel(
    const float* __restrict__ x, __nv_bfloat16* __restrict__ xh,
    __nv_bfloat16* __restrict__ xl, int n)
{
    int i = blockIdx.x * 256 + threadIdx.x;
    if (i < n) {
        float v = x[i];
        __nv_bfloat16 h = __float2bfloat16(v);
        xh[i] = h;
        xl[i] = __float2bfloat16(v - __bfloat162float(h));
    }
}

// ---------------- warp-MMA GEMM: C[M,N] = (Ah+Al) @ (Bh+Bl)^T + bias ----------------
// A*: [M,K] bf16 row-major.  B*: [N,K] bf16 row-major (pre-transposed weights).
// Block tile 64x64, BK=32, 128 threads (4 warps, 32x32 each).
// SMEM rows padded to 40 bf16 (80B) -> ldmatrix conflict-free.
// hi/lo 3-pass: acc += Ah*Bh + Ah*Bl + Al*Bh  (f32 accumulate).
#define PAD 40
#define TILE_B (64 * PAD * 2)           // 5120 bytes per tile
__global__ void __launch_bounds__(128) gemm_mma_kernel(
    const __nv_bfloat16* __restrict__ Ah, const __nv_bfloat16* __restrict__ Al,
    const __nv_bfloat16* __restrict__ Bh, const __nv_bfloat16* __restrict__ Bl,
    const float* __restrict__ bias, float* __restrict__ C, int N, int K)
{
    __shared__ __nv_bfloat16 smem[2 * 4 * 64 * PAD];   // 2 bufs x 4 tiles x 64 rows
    const uint32_t sbase = smem_u32(smem);

    const int tid = threadIdx.x;
    const int w = tid >> 5;
    const int t = tid & 31;
    const int m0 = (int)blockIdx.y * 64;
    const int n0 = (int)blockIdx.x * 64;
    const int mw = (w & 1) * 32;
    const int nw = (w >> 1) * 32;

    // prefetch slots: e in 0..7 -> tile = e>>1 (0:Ah 1:Al 2:Bh 3:Bl), slot = tid + (e&1)*128
    const __nv_bfloat16* srcs[4] = {Ah, Al, Bh, Bl};
    uint4 pf[8];
    int prow[8], pq[8];
    const __nv_bfloat16* pg[8];
#pragma unroll
    for (int e = 0; e < 8; e++) {
        int tile = e >> 1;
        int slot = tid + (e & 1) * 128;     // 0..255
        int row = slot >> 2, q = slot & 3;  // row 0..63, quarter 0..3
        prow[e] = row; pq[e] = q;
        int grow = (tile < 2) ? (m0 + row) : (n0 + row);
        pg[e] = srcs[tile] + (size_t)grow * K + q * 8;
    }

    float acc[2][4][4];
#pragma unroll
    for (int i = 0; i < 2; i++)
#pragma unroll
        for (int j = 0; j < 4; j++)
#pragma unroll
            for (int r = 0; r < 4; r++) acc[i][j][r] = 0.0f;

    // prologue prefetch (chunk 0)
#pragma unroll
    for (int e = 0; e < 8; e++) pf[e] = *(const uint4*)(pg[e]);

    const int nchunk = K >> 5;
    int buf = 0;
    for (int ct = 0; ct < nchunk; ct++) {
        // stage into smem[buf]
        uint32_t bb = sbase + buf * (4 * TILE_B);
#pragma unroll
        for (int e = 0; e < 8; e++) {
            uint32_t addr = bb + (e >> 1) * TILE_B + prow[e] * (PAD * 2) + pq[e] * 16;
            asm volatile("st.shared.v4.b32 [%0], {%1,%2,%3,%4};"
                         :: "r"(addr), "r"(pf[e].x), "r"(pf[e].y), "r"(pf[e].z), "r"(pf[e].w));
        }
        __syncthreads();

        // prefetch next chunk
        if (ct + 1 < nchunk) {
#pragma unroll
            for (int e = 0; e < 8; e++) pf[e] = *(const uint4*)(pg[e] + (ct + 1) * 32);
        }

        // compute from smem[buf]
        const uint32_t tAh = bb;
        const uint32_t tAl = bb + TILE_B;
        const uint32_t tBh = bb + 2 * TILE_B;
        const uint32_t tBl = bb + 3 * TILE_B;
#pragma unroll
        for (int kk = 0; kk < 2; kk++) {
            // B frags for this kk: 2 ldmatrix.x4 each for hi and lo
            uint32_t bhf[2][4], blf[2][4];
#pragma unroll
            for (int jp = 0; jp < 2; jp++) {
                int row = nw + jp * 16 + ((t >> 4) << 3) + (t & 7);
                int col = kk * 16 + (((t >> 3) & 1) << 3);
                uint32_t off = row * (PAD * 2) + col * 2;
                ldsm4(bhf[jp], tBh + off);
                ldsm4(blf[jp], tBl + off);
            }
#pragma unroll
            for (int i = 0; i < 2; i++) {
                int row = mw + i * 16 + (t & 7) + (((t >> 3) & 1) << 3);
                int col = kk * 16 + ((t >> 4) << 3);
                uint32_t off = row * (PAD * 2) + col * 2;
                uint32_t ahf[4], alf[4];
                ldsm4(ahf, tAh + off);
                ldsm4(alf, tAl + off);
#pragma unroll
                for (int j = 0; j < 4; j++) {
                    const uint32_t* bh2 = &bhf[j >> 1][(j & 1) * 2];
                    const uint32_t* bl2 = &blf[j >> 1][(j & 1) * 2];
                    mma16816(acc[i][j], ahf, bh2);
                    mma16816(acc[i][j], ahf, bl2);
                    mma16816(acc[i][j], alf, bh2);
                }
            }
        }
        buf ^= 1;
    }

    // epilogue: thread t owns rows {g, g+8}, col pair 2*(t&3) within each 16x8 atom
    const int g = t >> 2;
    const int cbase = n0 + nw + 2 * (t & 3);
#pragma unroll
    for (int i = 0; i < 2; i++) {
#pragma unroll
        for (int j = 0; j < 4; j++) {
            int c = cbase + j * 8;
            float2 bs = *(const float2*)(bias + c);
            int r0 = m0 + mw + i * 16 + g;
            float2 o0 = make_float2(acc[i][j][0] + bs.x, acc[i][j][1] + bs.y);
            float2 o1 = make_float2(acc[i][j][2] + bs.x, acc[i][j][3] + bs.y);
            *(float2*)&C[(size_t)r0 * N + c] = o0;
            *(float2*)&C[(size_t)(r0 + 8) * N + c] = o1;
        }
    }
}

// ---------------- scores + softmax ----------------
__global__ void __launch_bounds__(256) scores_softmax_kernel(
    const float* __restrict__ p_att, const float* __restrict__ att_h,
    const float* __restrict__ w_alpha, const float* __restrict__ b_alpha,
    float* __restrict__ weight)
{
    __shared__ float ah[1024];
    __shared__ float wa[512];
    __shared__ float sc[200];
    __shared__ float redm[8], reds[8];

    const int b = blockIdx.x;
    const int tid = threadIdx.x;
    for (int i = tid; i < 1024; i += 256) ah[i] = att_h[b * 1024 + i];
    for (int i = tid; i < 512; i += 256)  wa[i] = w_alpha[i];
    __syncthreads();

    const int lane = tid & 31, warp = tid >> 5;
    const float4* ah1 = (const float4*)ah;
    const float4* ah2 = ah1 + 128;
    const float4* wav = (const float4*)wa;
    const float balpha = b_alpha[0];

    for (int s = warp; s < 196; s += 8) {
        const float4* p = (const float4*)(p_att + ((size_t)b * 196 + s) * 1024);
        float sum = 0.0f;
#pragma unroll
        for (int i = 0; i < 4; i++) {
            int j = lane + (i << 5);
            float4 x = p[j];
            float4 y = p[j + 128];
            float4 a1 = ah1[j];
            float4 a2 = ah2[j];
            float4 w4 = wav[j];
            sum += gatef(x.x + a1.x, y.x + a2.x) * w4.x;
            sum += gatef(x.y + a1.y, y.y + a2.y) * w4.y;
            sum += gatef(x.z + a1.z, y.z + a2.z) * w4.z;
            sum += gatef(x.w + a1.w, y.w + a2.w) * w4.w;
        }
#pragma unroll
        for (int off = 16; off > 0; off >>= 1)
            sum += __shfl_xor_sync(0xffffffffu, sum, off);
        if (lane == 0) sc[s] = sum + balpha;
    }
    __syncthreads();

    float v = (tid < 196) ? sc[tid] : -1e30f;
    float m = v;
#pragma unroll
    for (int off = 16; off > 0; off >>= 1)
        m = fmaxf(m, __shfl_xor_sync(0xffffffffu, m, off));
    if (lane == 0) redm[warp] = m;
    __syncthreads();
    float mall = redm[0];
#pragma unroll
    for (int i = 1; i < 8; i++) mall = fmaxf(mall, redm[i]);

    float e = (tid < 196) ? fast_ex2(1.44269504f * (v - mall)) : 0.0f;
    float ssum = e;
#pragma unroll
    for (int off = 16; off > 0; off >>= 1)
        ssum += __shfl_xor_sync(0xffffffffu, ssum, off);
    if (lane == 0) reds[warp] = ssum;
    __syncthreads();
    float tot = 0.0f;
#pragma unroll
    for (int i = 0; i < 8; i++) tot += reds[i];

    if (tid < 196) weight[b * 196 + tid] = e / tot;
}

// ---------------- att_res = weight @ att_feats, output bf16 hi/lo ----------------
__global__ void __launch_bounds__(256) att_reduce_kernel(
    const float* __restrict__ att_feats, const float* __restrict__ weight,
    __nv_bfloat16* __restrict__ arh, __nv_bfloat16* __restrict__ arl)
{
    __shared__ float w[196];
    const int b = blockIdx.y;
    const int half = blockIdx.x;
    const int tid = threadIdx.x;
    for (int i = tid; i < 196; i += 256) w[i] = weight[b * 196 + i];
    __syncthreads();

    const float4* basep = (const float4*)(att_feats + (size_t)b * 196 * 2048 + half * 1024) + tid;
    float4 acc = make_float4(0.f, 0.f, 0.f, 0.f);
#pragma unroll 4
    for (int s = 0; s < 196; s++) {
        float4 vv = basep[(size_t)s * 512];
        float ws = w[s];
        acc.x += ws * vv.x; acc.y += ws * vv.y;
        acc.z += ws * vv.z; acc.w += ws * vv.w;
    }
    size_t o = (size_t)b * 2048 + half * 1024 + tid * 4;
    __nv_bfloat162 h0 = __floats2bfloat162_rn(acc.x, acc.y);
    __nv_bfloat162 h1 = __floats2bfloat162_rn(acc.z, acc.w);
    __nv_bfloat162 l0 = __floats2bfloat162_rn(acc.x - __low2float(h0), acc.y - __high2float(h0));
    __nv_bfloat162 l1 = __floats2bfloat162_rn(acc.z - __low2float(h1), acc.w - __high2float(h1));
    *(__nv_bfloat162*)(arh + o) = h0;
    *(__nv_bfloat162*)(arh + o + 2) = h1;
    *(__nv_bfloat162*)(arl + o) = l0;
    *(__nv_bfloat162*)(arl + o + 2) = l1;
}

// ---------------- final GLU gate (accurate math) ----------------
__global__ void __launch_bounds__(256) glu_kernel(
    const float* __restrict__ C, float* __restrict__ out)
{
    int idx = blockIdx.x * 256 + threadIdx.x;
    int b = idx >> 10, j = idx & 1023;
    float x = C[(size_t)b * 2048 + j];
    float y = C[(size_t)b * 2048 + 1024 + j];
    out[idx] = tanhf(x) * (1.0f / (1.0f + expf(-y)));
}

// ---------------- launch ----------------
extern "C" void kernel_launch(void* const* d_in, const int* in_sizes, int n_in,
                              void* d_out, int out_size)
{
    const float* h         = (const float*)d_in[0];
    const float* att_feats = (const float*)d_in[1];
    const float* p_att     = (const float*)d_in[2];
    const float* W_h2att   = (const float*)d_in[3];
    const float* b_h2att   = (const float*)d_in[4];
    const float* w_alpha   = (const float*)d_in[5];
    const float* b_alpha   = (const float*)d_in[6];
    const float* W_out     = (const float*)d_in[7];
    const float* b_out     = (const float*)d_in[8];
    float* out = (float*)d_out;

    float *att_h_p, *weight_p, *lin2_p;
    __nv_bfloat16 *WT1h, *WT1l, *WT2h, *WT2l, *hh, *hl, *arh, *arl;
    cudaGetSymbolAddress((void**)&att_h_p, g_att_h);
    cudaGetSymbolAddress((void**)&weight_p, g_weight);
    cudaGetSymbolAddress((void**)&lin2_p, g_lin2);
    cudaGetSymbolAddress((void**)&WT1h, g_WT1h);
    cudaGetSymbolAddress((void**)&WT1l, g_WT1l);
    cudaGetSymbolAddress((void**)&WT2h, g_WT2h);
    cudaGetSymbolAddress((void**)&WT2l, g_WT2l);
    cudaGetSymbolAddress((void**)&hh, g_hh);
    cudaGetSymbolAddress((void**)&hl, g_hl);
    cudaGetSymbolAddress((void**)&arh, g_arh);
    cudaGetSymbolAddress((void**)&arl, g_arl);

    // prep: transpose+split weights, split h
    prep_WT_kernel<<<dim3(32, 32), 256>>>(W_h2att, WT1h, WT1l, 1024, 1024);
    prep_WT_kernel<<<dim3(64, 64), 256>>>(W_out, WT2h, WT2l, 2048, 2048);
    prep_split_kernel<<<1024, 256>>>(h, hh, hl, 256 * 1024);

    // 1) att_h = h @ W_h2att + b   (M=256, N=1024, K=1024)
    gemm_mma_kernel<<<dim3(16, 4), 128>>>(hh, hl, WT1h, WT1l, b_h2att, att_h_p, 1024, 1024);
    // 2) gated scores + softmax
    scores_softmax_kernel<<<256, 256>>>(p_att, att_h_p, w_alpha, b_alpha, weight_p);
    // 3) att_res (bf16 hi/lo)
    att_reduce_kernel<<<dim3(2, 256), 256>>>(att_feats, weight_p, arh, arl);
    // 4) lin2 = att_res @ W_out + b (M=256, N=2048, K=2048)
    gemm_mma_kernel<<<dim3(32, 4), 128>>>(arh, arl, WT2h, WT2l, b_out, lin2_p, 2048, 2048);
    // 5) GLU
    glu_kernel<<<1024, 256>>>(lin2_p, out);
}